// round 1
// baseline (speedup 1.0000x reference)
#include <cuda_runtime.h>
#include <math.h>

static constexpr int T_   = 2048;
static constexpr int B_   = 2;
static constexpr int E_   = 1024;
static constexpr int H_   = 16;
static constexpr int HD_  = 64;
static constexpr int MTOK = T_ * B_;   // 4096
static constexpr int BH_  = B_ * H_;   // 32
static constexpr int N3E  = 3 * E_;    // 3072

// Scratch (static device globals: allocation-free at launch time)
__device__ float g_Q[(size_t)BH_ * T_ * HD_];
__device__ float g_K[(size_t)BH_ * T_ * HD_];
__device__ float g_V[(size_t)BH_ * T_ * HD_];
__device__ float g_P[(size_t)BH_ * T_ * T_];     // 536 MB probs buffer
__device__ float g_ATT[(size_t)MTOK * E_];

// ---------------------------------------------------------------------------
// Generic TN GEMM: C = A(MxK) @ B(NxK)^T, tile 128x128x8, 256 thr, 8x8/thread
// MODE 0: QKV projection epilogue (bias + scatter to g_Q/g_K/g_V, q*scale)
// MODE 1: out-proj epilogue (bias, write C row-major)
// MODE 2: batched scores (blockIdx.z selects (b,h)), write C, no bias
// ---------------------------------------------------------------------------
template <int MODE>
__global__ void __launch_bounds__(256) gemm_tn(
    const float* __restrict__ A, const float* __restrict__ Bm,
    const float* __restrict__ bias, float* __restrict__ C,
    int M, int N, int K)
{
    if (MODE == 2) {
        size_t z = blockIdx.z;
        A  += z * (size_t)T_ * HD_;
        Bm += z * (size_t)T_ * HD_;
        C  += z * (size_t)T_ * T_;
    }
    __shared__ float As[8][128];
    __shared__ float Bs[8][128];

    const int tid = threadIdx.x;
    const int i0 = blockIdx.y * 128;
    const int j0 = blockIdx.x * 128;
    const int tx = tid & 15;
    const int ty = tid >> 4;

    float acc[8][8];
    #pragma unroll
    for (int i = 0; i < 8; i++)
        #pragma unroll
        for (int j = 0; j < 8; j++) acc[i][j] = 0.f;

    const int arow = tid >> 1;        // 0..127
    const int acol = (tid & 1) * 4;   // 0 or 4
    const float* Aptr = A  + (size_t)(i0 + arow) * K + acol;
    const float* Bptr = Bm + (size_t)(j0 + arow) * K + acol;

    for (int kt = 0; kt < K; kt += 8) {
        float4 av = *(const float4*)(Aptr + kt);
        float4 bv = *(const float4*)(Bptr + kt);
        As[acol + 0][arow] = av.x; As[acol + 1][arow] = av.y;
        As[acol + 2][arow] = av.z; As[acol + 3][arow] = av.w;
        Bs[acol + 0][arow] = bv.x; Bs[acol + 1][arow] = bv.y;
        Bs[acol + 2][arow] = bv.z; Bs[acol + 3][arow] = bv.w;
        __syncthreads();
        #pragma unroll
        for (int k = 0; k < 8; k++) {
            float4 a0 = *(const float4*)&As[k][ty * 8];
            float4 a1 = *(const float4*)&As[k][ty * 8 + 4];
            float4 b0 = *(const float4*)&Bs[k][tx * 8];
            float4 b1 = *(const float4*)&Bs[k][tx * 8 + 4];
            float a[8] = {a0.x, a0.y, a0.z, a0.w, a1.x, a1.y, a1.z, a1.w};
            float b[8] = {b0.x, b0.y, b0.z, b0.w, b1.x, b1.y, b1.z, b1.w};
            #pragma unroll
            for (int i = 0; i < 8; i++)
                #pragma unroll
                for (int j = 0; j < 8; j++)
                    acc[i][j] = fmaf(a[i], b[j], acc[i][j]);
        }
        __syncthreads();
    }

    const int row0 = i0 + ty * 8;
    const int col0 = j0 + tx * 8;
    #pragma unroll
    for (int i = 0; i < 8; i++) {
        const int r = row0 + i;
        #pragma unroll
        for (int j = 0; j < 8; j++) {
            const int c = col0 + j;
            float v = acc[i][j];
            if (MODE == 0) {
                v += bias[c];
                const int t = r >> 1;       // B_ == 2
                const int b = r & 1;
                const int seg = c >> 10;    // / E_
                const int cc  = c & 1023;
                const int h = cc >> 6;
                const int d = cc & 63;
                const size_t off = (((size_t)(b * H_ + h) * T_ + t) * HD_) + d;
                if (seg == 0)      g_Q[off] = v * 0.125f;   // HD^-0.5
                else if (seg == 1) g_K[off] = v;
                else               g_V[off] = v;
            } else if (MODE == 1) {
                C[(size_t)r * N + c] = v + bias[c];
            } else {
                C[(size_t)r * N + c] = v;
            }
        }
    }
}

// ---------------------------------------------------------------------------
// Row softmax over P: one block per row of length T_=2048
// ---------------------------------------------------------------------------
__global__ void __launch_bounds__(256) softmax_rows(float* __restrict__ P)
{
    float* p = P + (size_t)blockIdx.x * T_;
    const int tid = threadIdx.x;
    float4 v0 = ((const float4*)p)[tid];
    float4 v1 = ((const float4*)p)[tid + 256];

    float m = fmaxf(fmaxf(fmaxf(v0.x, v0.y), fmaxf(v0.z, v0.w)),
                    fmaxf(fmaxf(v1.x, v1.y), fmaxf(v1.z, v1.w)));
    __shared__ float red[8];
    #pragma unroll
    for (int o = 16; o; o >>= 1) m = fmaxf(m, __shfl_xor_sync(0xffffffffu, m, o));
    if ((tid & 31) == 0) red[tid >> 5] = m;
    __syncthreads();
    {
        float t = red[tid & 7];
        #pragma unroll
        for (int o = 4; o; o >>= 1) t = fmaxf(t, __shfl_xor_sync(0xffffffffu, t, o));
        m = t;
    }
    __syncthreads();

    v0.x = expf(v0.x - m); v0.y = expf(v0.y - m);
    v0.z = expf(v0.z - m); v0.w = expf(v0.w - m);
    v1.x = expf(v1.x - m); v1.y = expf(v1.y - m);
    v1.z = expf(v1.z - m); v1.w = expf(v1.w - m);

    float s = v0.x + v0.y + v0.z + v0.w + v1.x + v1.y + v1.z + v1.w;
    #pragma unroll
    for (int o = 16; o; o >>= 1) s += __shfl_xor_sync(0xffffffffu, s, o);
    if ((tid & 31) == 0) red[tid >> 5] = s;
    __syncthreads();
    {
        float t = red[tid & 7];
        #pragma unroll
        for (int o = 4; o; o >>= 1) t += __shfl_xor_sync(0xffffffffu, t, o);
        s = t;
    }

    const float inv = 1.0f / s;
    v0.x *= inv; v0.y *= inv; v0.z *= inv; v0.w *= inv;
    v1.x *= inv; v1.y *= inv; v1.z *= inv; v1.w *= inv;
    ((float4*)p)[tid]       = v0;
    ((float4*)p)[tid + 256] = v1;
}

// ---------------------------------------------------------------------------
// attn_weights[b,tq,ts] = (1/H) * sum_h P[b,h,tq,ts]
// ---------------------------------------------------------------------------
__global__ void __launch_bounds__(256) head_sum(const float* __restrict__ P,
                                                float* __restrict__ W)
{
    const size_t idx = (size_t)blockIdx.x * blockDim.x + threadIdx.x;   // float4 units
    const size_t per_b = (size_t)T_ * T_ / 4;
    const size_t total = (size_t)B_ * per_b;
    if (idx >= total) return;
    const size_t b   = idx / per_b;
    const size_t rem = idx % per_b;
    const float4* base = (const float4*)P + b * H_ * per_b + rem;
    float4 s = make_float4(0.f, 0.f, 0.f, 0.f);
    #pragma unroll
    for (int h = 0; h < H_; h++) {
        float4 x = base[(size_t)h * per_b];
        s.x += x.x; s.y += x.y; s.z += x.z; s.w += x.w;
    }
    const float sc = 1.0f / (float)H_;
    s.x *= sc; s.y *= sc; s.z *= sc; s.w *= sc;
    ((float4*)W)[idx] = s;
}

// ---------------------------------------------------------------------------
// PV GEMM per (b,h): O[128-row tile, 64] = P[128,2048] @ V[2048,64]
// Writes directly into [T,B,E] layout of g_ATT.
// ---------------------------------------------------------------------------
__global__ void __launch_bounds__(256) pv_gemm(const float* __restrict__ P,
                                               const float* __restrict__ V,
                                               float* __restrict__ out)
{
    __shared__ float Ps[16][128];
    __shared__ float Vs[16][64];

    const int bh = blockIdx.y;
    const int b  = bh >> 4;      // / H_
    const int h  = bh & 15;
    const float* Pp = P + (size_t)bh * T_ * T_ + (size_t)blockIdx.x * 128 * T_;
    const float* Vp = V + (size_t)bh * T_ * HD_;

    const int tid = threadIdx.x;
    const int tx = tid & 15;
    const int ty = tid >> 4;

    float acc[8][4];
    #pragma unroll
    for (int i = 0; i < 8; i++)
        #pragma unroll
        for (int j = 0; j < 4; j++) acc[i][j] = 0.f;

    for (int kt = 0; kt < T_; kt += 16) {
        #pragma unroll
        for (int q = 0; q < 2; q++) {
            const int ff  = tid * 2 + q;
            const int row = ff >> 2;          // 0..127
            const int kq  = (ff & 3) * 4;
            float4 pv4 = *(const float4*)(Pp + (size_t)row * T_ + kt + kq);
            Ps[kq + 0][row] = pv4.x; Ps[kq + 1][row] = pv4.y;
            Ps[kq + 2][row] = pv4.z; Ps[kq + 3][row] = pv4.w;
        }
        {
            const int row = tid >> 4;          // 0..15
            const int c   = (tid & 15) * 4;
            *(float4*)&Vs[row][c] = *(const float4*)(Vp + (size_t)(kt + row) * HD_ + c);
        }
        __syncthreads();
        #pragma unroll
        for (int k = 0; k < 16; k++) {
            float4 a0 = *(const float4*)&Ps[k][ty * 8];
            float4 a1 = *(const float4*)&Ps[k][ty * 8 + 4];
            float4 bb = *(const float4*)&Vs[k][tx * 4];
            float a[8] = {a0.x, a0.y, a0.z, a0.w, a1.x, a1.y, a1.z, a1.w};
            float bv[4] = {bb.x, bb.y, bb.z, bb.w};
            #pragma unroll
            for (int i = 0; i < 8; i++)
                #pragma unroll
                for (int j = 0; j < 4; j++)
                    acc[i][j] = fmaf(a[i], bv[j], acc[i][j]);
        }
        __syncthreads();
    }

    const int r0 = blockIdx.x * 128 + ty * 8;
    const int c0 = tx * 4;
    #pragma unroll
    for (int i = 0; i < 8; i++) {
        const int t = r0 + i;
        const size_t o = ((size_t)t * B_ + b) * E_ + h * HD_ + c0;
        float4 w = make_float4(acc[i][0], acc[i][1], acc[i][2], acc[i][3]);
        *(float4*)&out[o] = w;
    }
}

// ---------------------------------------------------------------------------
extern "C" void kernel_launch(void* const* d_in, const int* in_sizes, int n_in,
                              void* d_out, int out_size)
{
    const float* x     = (const float*)d_in[0];
    const float* in_w  = (const float*)d_in[1];
    const float* in_b  = (const float*)d_in[2];
    const float* out_w = (const float*)d_in[3];
    const float* out_b = (const float*)d_in[4];

    float* attn_out = (float*)d_out;                        // [T,B,E]
    float* w_out    = (float*)d_out + (size_t)MTOK * E_;    // [B,T,T]

    float *Q, *K, *V, *P, *ATT;
    cudaGetSymbolAddress((void**)&Q,   g_Q);
    cudaGetSymbolAddress((void**)&K,   g_K);
    cudaGetSymbolAddress((void**)&V,   g_V);
    cudaGetSymbolAddress((void**)&P,   g_P);
    cudaGetSymbolAddress((void**)&ATT, g_ATT);

    // 1) QKV projection (scatters into g_Q/g_K/g_V, q pre-scaled)
    gemm_tn<0><<<dim3(N3E / 128, MTOK / 128), 256>>>(x, in_w, in_b, nullptr,
                                                     MTOK, N3E, E_);
    // 2) scores = Q @ K^T per (b,h)
    gemm_tn<2><<<dim3(T_ / 128, T_ / 128, BH_), 256>>>(Q, K, nullptr, P,
                                                       T_, T_, HD_);
    // 3) row softmax in-place on P
    softmax_rows<<<BH_ * T_, 256>>>(P);
    // 4) head-averaged attention weights -> second output
    {
        const size_t total4 = (size_t)B_ * T_ * T_ / 4;
        head_sum<<<(unsigned)((total4 + 255) / 256), 256>>>(P, w_out);
    }
    // 5) O = P @ V, written in [T,B,E] layout
    pv_gemm<<<dim3(T_ / 128, BH_), 256>>>(P, V, ATT);
    // 6) out projection -> first output
    gemm_tn<1><<<dim3(E_ / 128, MTOK / 128), 256>>>(ATT, out_w, out_b, attn_out,
                                                    MTOK, E_, E_);
}

// round 2
// speedup vs baseline: 2.6422x; 2.6422x over previous
#include <cuda_runtime.h>
#include <math.h>
#include <stdint.h>

static constexpr int T_   = 2048;
static constexpr int B_   = 2;
static constexpr int E_   = 1024;
static constexpr int H_   = 16;
static constexpr int HD_  = 64;
static constexpr int MTOK = T_ * B_;   // 4096
static constexpr int BH_  = B_ * H_;   // 32
static constexpr int N3E  = 3 * E_;    // 3072

// Scratch (static device globals: allocation-free at launch time)
__device__ float g_Q[(size_t)BH_ * T_ * HD_];
__device__ float g_K[(size_t)BH_ * T_ * HD_];
__device__ float g_V[(size_t)BH_ * T_ * HD_];
__device__ float g_P[(size_t)BH_ * T_ * T_];     // 536 MB probs buffer
__device__ float g_ATT[(size_t)MTOK * E_];

__device__ __forceinline__ uint32_t f2tf32(float f) {
    uint32_t r;
    asm("cvt.rna.tf32.f32 %0, %1;" : "=r"(r) : "f"(f));
    return r;
}

__device__ __forceinline__ void mma_tf32(float* d, const uint32_t* a, const uint32_t* b) {
    asm volatile(
        "mma.sync.aligned.m16n8k8.row.col.f32.tf32.tf32.f32 "
        "{%0,%1,%2,%3}, {%4,%5,%6,%7}, {%8,%9}, {%0,%1,%2,%3};"
        : "+f"(d[0]), "+f"(d[1]), "+f"(d[2]), "+f"(d[3])
        : "r"(a[0]), "r"(a[1]), "r"(a[2]), "r"(a[3]), "r"(b[0]), "r"(b[1]));
}

// ---------------------------------------------------------------------------
// TF32 tensor-core GEMM. C = A(MxK) @ op(B), fp32 accumulate.
//  BTRANS=true : B given as (N x K) row-major (i.e. C = A B^T)
//  BTRANS=false: B given as (K x N) row-major (PV case)
// MODE 0: QKV epilogue (bias + scatter to g_Q/g_K/g_V, q*scale)
// MODE 1: out-proj epilogue (bias, row-major C)
// MODE 2: batched scores (blockIdx.z = (b,h)), row-major C
// MODE 3: batched PV, scatter to [T,B,E]
// Block: BM x BN x 32, 256 threads, warp tile WM x WN, mma m16n8k8.
// ---------------------------------------------------------------------------
template <int BM, int BN, int WM, int WN, int MODE, bool BTRANS>
__global__ void __launch_bounds__(256) gemm_mma(
    const float* __restrict__ A, const float* __restrict__ Bm,
    const float* __restrict__ bias, float* __restrict__ C,
    int M, int N, int K)
{
    constexpr int KC = 32;
    constexpr int WARPS_N = BN / WN;
    constexpr int MT = WM / 16;
    constexpr int NT = WN / 8;
    constexpr int AV = BM * KC / 1024;                       // float4s per thread (A)
    constexpr int BV = BN * KC / 1024;                       // float4s per thread (B)

    // A chunk stored [m][k], pad 36 (frag-load banks = lane -> conflict-free)
    __shared__ uint32_t As[BM][36];
    // B chunk: BTRANS -> [n][k] pad 36 ; !BTRANS -> [k][n] pad BN+8
    __shared__ uint32_t Bs[BTRANS ? BN : KC][BTRANS ? 36 : (BN + 8)];

    const float* Ab = A;
    const float* Bb = Bm;
    if (MODE == 2) {
        size_t z = blockIdx.z;
        Ab += z * (size_t)T_ * HD_;
        Bb += z * (size_t)T_ * HD_;
    }
    if (MODE == 3) {
        size_t z = blockIdx.z;
        Ab += z * (size_t)T_ * T_;
        Bb += z * (size_t)T_ * HD_;
    }

    const int tid  = threadIdx.x;
    const int lane = tid & 31;
    const int warp = tid >> 5;
    const int wm   = warp / WARPS_N;
    const int wn   = warp % WARPS_N;
    const int i0   = blockIdx.y * BM;
    const int j0   = blockIdx.x * BN;
    const int lc   = lane & 3;   // k%4 within fragment
    const int lg   = lane >> 2;  // 0..7

    float acc[MT][NT][4];
    #pragma unroll
    for (int i = 0; i < MT; i++)
        #pragma unroll
        for (int j = 0; j < NT; j++)
            #pragma unroll
            for (int q = 0; q < 4; q++) acc[i][j][q] = 0.f;

    float4 ap[AV], bp[BV];

    auto loadA = [&](int kt) {
        #pragma unroll
        for (int v = 0; v < AV; v++) {
            int f = tid + v * 256;
            int row = f >> 3;            // KC/4 = 8 float4 per row
            int k4  = (f & 7) << 2;
            ap[v] = *(const float4*)(Ab + (size_t)(i0 + row) * K + kt + k4);
        }
    };
    auto storeA = [&]() {
        #pragma unroll
        for (int v = 0; v < AV; v++) {
            int f = tid + v * 256;
            int row = f >> 3;
            int k4  = (f & 7) << 2;
            uint4 u;
            u.x = f2tf32(ap[v].x); u.y = f2tf32(ap[v].y);
            u.z = f2tf32(ap[v].z); u.w = f2tf32(ap[v].w);
            *(uint4*)&As[row][k4] = u;
        }
    };
    auto loadB = [&](int kt) {
        #pragma unroll
        for (int v = 0; v < BV; v++) {
            int f = tid + v * 256;
            if (BTRANS) {
                int row = f >> 3;
                int k4  = (f & 7) << 2;
                bp[v] = *(const float4*)(Bb + (size_t)(j0 + row) * K + kt + k4);
            } else {
                int krow = f >> 4;               // BN/4 = 16 float4 per k-row
                int n4   = (f & 15) << 2;
                bp[v] = *(const float4*)(Bb + (size_t)(kt + krow) * N + j0 + n4);
            }
        }
    };
    auto storeB = [&]() {
        #pragma unroll
        for (int v = 0; v < BV; v++) {
            int f = tid + v * 256;
            uint4 u;
            u.x = f2tf32(bp[v].x); u.y = f2tf32(bp[v].y);
            u.z = f2tf32(bp[v].z); u.w = f2tf32(bp[v].w);
            if (BTRANS) {
                int row = f >> 3;
                int k4  = (f & 7) << 2;
                *(uint4*)&Bs[row][k4] = u;
            } else {
                int krow = f >> 4;
                int n4   = (f & 15) << 2;
                *(uint4*)&Bs[krow][n4] = u;
            }
        }
    };

    loadA(0);
    loadB(0);

    for (int kt = 0; kt < K; kt += KC) {
        storeA();
        storeB();
        __syncthreads();
        if (kt + KC < K) { loadA(kt + KC); loadB(kt + KC); }

        #pragma unroll
        for (int s = 0; s < KC / 8; s++) {
            const int kb = s * 8;
            uint32_t af[MT][4];
            uint32_t bf[NT][2];
            #pragma unroll
            for (int i = 0; i < MT; i++) {
                int r = wm * WM + i * 16 + lg;
                af[i][0] = As[r][kb + lc];
                af[i][1] = As[r + 8][kb + lc];
                af[i][2] = As[r][kb + lc + 4];
                af[i][3] = As[r + 8][kb + lc + 4];
            }
            #pragma unroll
            for (int j = 0; j < NT; j++) {
                int n = wn * WN + j * 8 + lg;
                if (BTRANS) {
                    bf[j][0] = Bs[n][kb + lc];
                    bf[j][1] = Bs[n][kb + lc + 4];
                } else {
                    bf[j][0] = Bs[kb + lc][n];
                    bf[j][1] = Bs[kb + lc + 4][n];
                }
            }
            #pragma unroll
            for (int i = 0; i < MT; i++)
                #pragma unroll
                for (int j = 0; j < NT; j++)
                    mma_tf32(acc[i][j], af[i], bf[j]);
        }
        __syncthreads();
    }

    // Epilogue: tile (i,j) elem q -> row/col
    #pragma unroll
    for (int i = 0; i < MT; i++) {
        #pragma unroll
        for (int j = 0; j < NT; j++) {
            const int r_lo = i0 + wm * WM + i * 16 + lg;
            const int c_lo = j0 + wn * WN + j * 8 + lc * 2;
            #pragma unroll
            for (int q = 0; q < 4; q++) {
                const int r = r_lo + (q >> 1) * 8;
                const int c = c_lo + (q & 1);
                float v = acc[i][j][q];
                if (MODE == 0) {
                    v += __ldg(&bias[c]);
                    const int t   = r >> 1;      // B_ == 2
                    const int b   = r & 1;
                    const int seg = c >> 10;
                    const int cc  = c & 1023;
                    const int h   = cc >> 6;
                    const int d   = cc & 63;
                    const size_t off = (((size_t)(b * H_ + h) * T_ + t) * HD_) + d;
                    if (seg == 0)      g_Q[off] = v * 0.125f;
                    else if (seg == 1) g_K[off] = v;
                    else               g_V[off] = v;
                } else if (MODE == 1) {
                    C[(size_t)r * N + c] = v + __ldg(&bias[c]);
                } else if (MODE == 2) {
                    (C + (size_t)blockIdx.z * T_ * T_)[(size_t)r * T_ + c] = v;
                } else { // MODE 3: PV -> [T,B,E]
                    const int z = blockIdx.z;
                    const int b = z >> 4;
                    const int h = z & 15;
                    C[((size_t)r * B_ + b) * E_ + h * HD_ + c] = v;
                }
            }
        }
    }
}

// ---------------------------------------------------------------------------
// Row softmax over P: one block per row of length T_=2048
// ---------------------------------------------------------------------------
__global__ void __launch_bounds__(256) softmax_rows(float* __restrict__ P)
{
    float* p = P + (size_t)blockIdx.x * T_;
    const int tid = threadIdx.x;
    float4 v0 = ((const float4*)p)[tid];
    float4 v1 = ((const float4*)p)[tid + 256];

    float m = fmaxf(fmaxf(fmaxf(v0.x, v0.y), fmaxf(v0.z, v0.w)),
                    fmaxf(fmaxf(v1.x, v1.y), fmaxf(v1.z, v1.w)));
    __shared__ float red[8];
    #pragma unroll
    for (int o = 16; o; o >>= 1) m = fmaxf(m, __shfl_xor_sync(0xffffffffu, m, o));
    if ((tid & 31) == 0) red[tid >> 5] = m;
    __syncthreads();
    {
        float t = red[tid & 7];
        #pragma unroll
        for (int o = 4; o; o >>= 1) t = fmaxf(t, __shfl_xor_sync(0xffffffffu, t, o));
        m = t;
    }
    __syncthreads();

    v0.x = expf(v0.x - m); v0.y = expf(v0.y - m);
    v0.z = expf(v0.z - m); v0.w = expf(v0.w - m);
    v1.x = expf(v1.x - m); v1.y = expf(v1.y - m);
    v1.z = expf(v1.z - m); v1.w = expf(v1.w - m);

    float s = v0.x + v0.y + v0.z + v0.w + v1.x + v1.y + v1.z + v1.w;
    #pragma unroll
    for (int o = 16; o; o >>= 1) s += __shfl_xor_sync(0xffffffffu, s, o);
    if ((tid & 31) == 0) red[tid >> 5] = s;
    __syncthreads();
    {
        float t = red[tid & 7];
        #pragma unroll
        for (int o = 4; o; o >>= 1) t += __shfl_xor_sync(0xffffffffu, t, o);
        s = t;
    }

    const float inv = 1.0f / s;
    v0.x *= inv; v0.y *= inv; v0.z *= inv; v0.w *= inv;
    v1.x *= inv; v1.y *= inv; v1.z *= inv; v1.w *= inv;
    ((float4*)p)[tid]       = v0;
    ((float4*)p)[tid + 256] = v1;
}

// ---------------------------------------------------------------------------
// attn_weights[b,tq,ts] = (1/H) * sum_h P[b,h,tq,ts]
// ---------------------------------------------------------------------------
__global__ void __launch_bounds__(256) head_sum(const float* __restrict__ P,
                                                float* __restrict__ W)
{
    const size_t idx = (size_t)blockIdx.x * blockDim.x + threadIdx.x;   // float4 units
    const size_t per_b = (size_t)T_ * T_ / 4;
    const size_t total = (size_t)B_ * per_b;
    if (idx >= total) return;
    const size_t b   = idx / per_b;
    const size_t rem = idx % per_b;
    const float4* base = (const float4*)P + b * H_ * per_b + rem;
    float4 s = make_float4(0.f, 0.f, 0.f, 0.f);
    #pragma unroll
    for (int h = 0; h < H_; h++) {
        float4 x = base[(size_t)h * per_b];
        s.x += x.x; s.y += x.y; s.z += x.z; s.w += x.w;
    }
    const float sc = 1.0f / (float)H_;
    s.x *= sc; s.y *= sc; s.z *= sc; s.w *= sc;
    ((float4*)W)[idx] = s;
}

// ---------------------------------------------------------------------------
extern "C" void kernel_launch(void* const* d_in, const int* in_sizes, int n_in,
                              void* d_out, int out_size)
{
    const float* x     = (const float*)d_in[0];
    const float* in_w  = (const float*)d_in[1];
    const float* in_b  = (const float*)d_in[2];
    const float* out_w = (const float*)d_in[3];
    const float* out_b = (const float*)d_in[4];

    float* attn_out = (float*)d_out;                        // [T,B,E]
    float* w_out    = (float*)d_out + (size_t)MTOK * E_;    // [B,T,T]

    float *Q, *K, *V, *P, *ATT;
    cudaGetSymbolAddress((void**)&Q,   g_Q);
    cudaGetSymbolAddress((void**)&K,   g_K);
    cudaGetSymbolAddress((void**)&V,   g_V);
    cudaGetSymbolAddress((void**)&P,   g_P);
    cudaGetSymbolAddress((void**)&ATT, g_ATT);

    // 1) QKV projection (tf32 mma) -> g_Q/g_K/g_V
    gemm_mma<128,128,64,32,0,true><<<dim3(N3E/128, MTOK/128), 256>>>(
        x, in_w, in_b, nullptr, MTOK, N3E, E_);
    // 2) scores = Q @ K^T per (b,h)
    gemm_mma<128,128,64,32,2,true><<<dim3(T_/128, T_/128, BH_), 256>>>(
        Q, K, nullptr, P, T_, T_, HD_);
    // 3) row softmax in-place on P
    softmax_rows<<<BH_ * T_, 256>>>(P);
    // 4) head-averaged attention weights -> second output
    {
        const size_t total4 = (size_t)B_ * T_ * T_ / 4;
        head_sum<<<(unsigned)((total4 + 255) / 256), 256>>>(P, w_out);
    }
    // 5) O = P @ V, written in [T,B,E] layout
    gemm_mma<128,64,32,32,3,false><<<dim3(1, T_/128, BH_), 256>>>(
        P, V, nullptr, ATT, T_, HD_, T_);
    // 6) out projection -> first output
    gemm_mma<128,128,64,32,1,true><<<dim3(E_/128, MTOK/128), 256>>>(
        ATT, out_w, out_b, attn_out, MTOK, E_, E_);
}

// round 3
// speedup vs baseline: 3.0476x; 1.1534x over previous
#include <cuda_runtime.h>
#include <math.h>
#include <stdint.h>

static constexpr int T_   = 2048;
static constexpr int B_   = 2;
static constexpr int E_   = 1024;
static constexpr int H_   = 16;
static constexpr int HD_  = 64;
static constexpr int MTOK = T_ * B_;   // 4096
static constexpr int BH_  = B_ * H_;   // 32
static constexpr int N3E  = 3 * E_;    // 3072
static constexpr int NTILE = T_ / 128; // 16 score col-tiles per row

// Scratch (static device globals: allocation-free at launch time)
__device__ float g_Q[(size_t)BH_ * T_ * HD_];
__device__ float g_K[(size_t)BH_ * T_ * HD_];
__device__ float g_V[(size_t)BH_ * T_ * HD_];
__device__ float g_P[(size_t)BH_ * T_ * T_];      // unnormalized exp(scores)
__device__ float g_ATT[(size_t)MTOK * E_];
__device__ float g_psum[(size_t)BH_ * T_ * NTILE]; // per-tile row partial sums
__device__ float g_rsi[(size_t)BH_ * T_];          // 1 / rowsum

__device__ __forceinline__ uint32_t f2tf32(float f) {
    uint32_t r;
    asm("cvt.rna.tf32.f32 %0, %1;" : "=r"(r) : "f"(f));
    return r;
}

__device__ __forceinline__ void mma_tf32(float* d, const uint32_t* a, const uint32_t* b) {
    asm volatile(
        "mma.sync.aligned.m16n8k8.row.col.f32.tf32.tf32.f32 "
        "{%0,%1,%2,%3}, {%4,%5,%6,%7}, {%8,%9}, {%0,%1,%2,%3};"
        : "+f"(d[0]), "+f"(d[1]), "+f"(d[2]), "+f"(d[3])
        : "r"(a[0]), "r"(a[1]), "r"(a[2]), "r"(a[3]), "r"(b[0]), "r"(b[1]));
}

// ---------------------------------------------------------------------------
// TF32 tensor-core GEMM. C = A(MxK) @ op(B), fp32 accumulate.
//  BTRANS=true : B given as (N x K) row-major (C = A B^T)
//  BTRANS=false: B given as (K x N) row-major (PV case)
// MODE 0: QKV epilogue (bias + scatter to g_Q/g_K/g_V, q*scale)
// MODE 1: out-proj epilogue (bias, row-major C)
// MODE 2: batched scores: exp() fused, write unnormalized expS,
//         deterministic per-row partial sums -> g_psum
// MODE 3: batched PV, scale rows by g_rsi, scatter to [T,B,E]
// ---------------------------------------------------------------------------
template <int BM, int BN, int WM, int WN, int MODE, bool BTRANS>
__global__ void __launch_bounds__(256) gemm_mma(
    const float* __restrict__ A, const float* __restrict__ Bm,
    const float* __restrict__ bias, float* __restrict__ C,
    int M, int N, int K)
{
    constexpr int KC = 32;
    constexpr int WARPS_N = BN / WN;
    constexpr int MT = WM / 16;
    constexpr int NT = WN / 8;
    constexpr int AV = BM * KC / 1024;
    constexpr int BV = BN * KC / 1024;

    __shared__ uint32_t As[BM][36];
    __shared__ uint32_t Bs[BTRANS ? BN : KC][BTRANS ? 36 : (BN + 8)];
    __shared__ float Ssum[MODE == 2 ? BM : 1][MODE == 2 ? WARPS_N : 1];

    const float* Ab = A;
    const float* Bb = Bm;
    if (MODE == 2) {
        size_t z = blockIdx.z;
        Ab += z * (size_t)T_ * HD_;
        Bb += z * (size_t)T_ * HD_;
    }
    if (MODE == 3) {
        size_t z = blockIdx.z;
        Ab += z * (size_t)T_ * T_;
        Bb += z * (size_t)T_ * HD_;
    }

    const int tid  = threadIdx.x;
    const int lane = tid & 31;
    const int warp = tid >> 5;
    const int wm   = warp / WARPS_N;
    const int wn   = warp % WARPS_N;
    const int i0   = blockIdx.y * BM;
    const int j0   = blockIdx.x * BN;
    const int lc   = lane & 3;
    const int lg   = lane >> 2;

    float acc[MT][NT][4];
    #pragma unroll
    for (int i = 0; i < MT; i++)
        #pragma unroll
        for (int j = 0; j < NT; j++)
            #pragma unroll
            for (int q = 0; q < 4; q++) acc[i][j][q] = 0.f;

    float4 ap[AV], bp[BV];

    auto loadA = [&](int kt) {
        #pragma unroll
        for (int v = 0; v < AV; v++) {
            int f = tid + v * 256;
            int row = f >> 3;
            int k4  = (f & 7) << 2;
            ap[v] = *(const float4*)(Ab + (size_t)(i0 + row) * K + kt + k4);
        }
    };
    auto storeA = [&]() {
        #pragma unroll
        for (int v = 0; v < AV; v++) {
            int f = tid + v * 256;
            int row = f >> 3;
            int k4  = (f & 7) << 2;
            uint4 u;
            u.x = f2tf32(ap[v].x); u.y = f2tf32(ap[v].y);
            u.z = f2tf32(ap[v].z); u.w = f2tf32(ap[v].w);
            *(uint4*)&As[row][k4] = u;
        }
    };
    auto loadB = [&](int kt) {
        #pragma unroll
        for (int v = 0; v < BV; v++) {
            int f = tid + v * 256;
            if (BTRANS) {
                int row = f >> 3;
                int k4  = (f & 7) << 2;
                bp[v] = *(const float4*)(Bb + (size_t)(j0 + row) * K + kt + k4);
            } else {
                int krow = f >> 4;
                int n4   = (f & 15) << 2;
                bp[v] = *(const float4*)(Bb + (size_t)(kt + krow) * N + j0 + n4);
            }
        }
    };
    auto storeB = [&]() {
        #pragma unroll
        for (int v = 0; v < BV; v++) {
            int f = tid + v * 256;
            uint4 u;
            u.x = f2tf32(bp[v].x); u.y = f2tf32(bp[v].y);
            u.z = f2tf32(bp[v].z); u.w = f2tf32(bp[v].w);
            if (BTRANS) {
                int row = f >> 3;
                int k4  = (f & 7) << 2;
                *(uint4*)&Bs[row][k4] = u;
            } else {
                int krow = f >> 4;
                int n4   = (f & 15) << 2;
                *(uint4*)&Bs[krow][n4] = u;
            }
        }
    };

    loadA(0);
    loadB(0);

    for (int kt = 0; kt < K; kt += KC) {
        storeA();
        storeB();
        __syncthreads();
        if (kt + KC < K) { loadA(kt + KC); loadB(kt + KC); }

        #pragma unroll
        for (int s = 0; s < KC / 8; s++) {
            const int kb = s * 8;
            uint32_t af[MT][4];
            uint32_t bf[NT][2];
            #pragma unroll
            for (int i = 0; i < MT; i++) {
                int r = wm * WM + i * 16 + lg;
                af[i][0] = As[r][kb + lc];
                af[i][1] = As[r + 8][kb + lc];
                af[i][2] = As[r][kb + lc + 4];
                af[i][3] = As[r + 8][kb + lc + 4];
            }
            #pragma unroll
            for (int j = 0; j < NT; j++) {
                int n = wn * WN + j * 8 + lg;
                if (BTRANS) {
                    bf[j][0] = Bs[n][kb + lc];
                    bf[j][1] = Bs[n][kb + lc + 4];
                } else {
                    bf[j][0] = Bs[kb + lc][n];
                    bf[j][1] = Bs[kb + lc + 4][n];
                }
            }
            #pragma unroll
            for (int i = 0; i < MT; i++)
                #pragma unroll
                for (int j = 0; j < NT; j++)
                    mma_tf32(acc[i][j], af[i], bf[j]);
        }
        __syncthreads();
    }

    // --- Epilogue ---
    float rowpart[MODE == 2 ? MT : 1][MODE == 2 ? 2 : 1];
    if (MODE == 2) {
        #pragma unroll
        for (int i = 0; i < MT; i++) { rowpart[i][0] = 0.f; rowpart[i][1] = 0.f; }
    }

    #pragma unroll
    for (int i = 0; i < MT; i++) {
        #pragma unroll
        for (int j = 0; j < NT; j++) {
            const int r_lo = i0 + wm * WM + i * 16 + lg;
            const int c_lo = j0 + wn * WN + j * 8 + lc * 2;
            #pragma unroll
            for (int q = 0; q < 4; q++) {
                const int r = r_lo + (q >> 1) * 8;
                const int c = c_lo + (q & 1);
                float v = acc[i][j][q];
                if (MODE == 0) {
                    v += __ldg(&bias[c]);
                    const int t   = r >> 1;      // B_ == 2
                    const int b   = r & 1;
                    const int seg = c >> 10;
                    const int cc  = c & 1023;
                    const int h   = cc >> 6;
                    const int d   = cc & 63;
                    const size_t off = (((size_t)(b * H_ + h) * T_ + t) * HD_) + d;
                    if (seg == 0)      g_Q[off] = v * 0.125f;
                    else if (seg == 1) g_K[off] = v;
                    else               g_V[off] = v;
                } else if (MODE == 1) {
                    C[(size_t)r * N + c] = v + __ldg(&bias[c]);
                } else if (MODE == 2) {
                    float ev = __expf(v);
                    (C + (size_t)blockIdx.z * T_ * T_)[(size_t)r * T_ + c] = ev;
                    rowpart[i][q >> 1] += ev;
                } else { // MODE 3
                    const int z = blockIdx.z;
                    const int b = z >> 4;
                    const int h = z & 15;
                    const float inv = g_rsi[(size_t)z * T_ + r];
                    C[((size_t)r * B_ + b) * E_ + h * HD_ + c] = v * inv;
                }
            }
        }
    }

    if (MODE == 2) {
        // reduce over lc (lane bits 0..1): fixed order -> deterministic
        #pragma unroll
        for (int i = 0; i < MT; i++) {
            #pragma unroll
            for (int qh = 0; qh < 2; qh++) {
                float s = rowpart[i][qh];
                s += __shfl_xor_sync(0xffffffffu, s, 1);
                s += __shfl_xor_sync(0xffffffffu, s, 2);
                rowpart[i][qh] = s;
            }
        }
        if (lc == 0) {
            #pragma unroll
            for (int i = 0; i < MT; i++)
                #pragma unroll
                for (int qh = 0; qh < 2; qh++) {
                    int rl = wm * WM + i * 16 + qh * 8 + lg;
                    Ssum[rl][wn] = rowpart[i][qh];
                }
        }
        __syncthreads();
        if (tid < BM) {
            float s = 0.f;
            #pragma unroll
            for (int w = 0; w < WARPS_N; w++) s += Ssum[tid][w];
            g_psum[((size_t)blockIdx.z * T_ + i0 + tid) * NTILE + blockIdx.x] = s;
        }
    }
}

// ---------------------------------------------------------------------------
// inv rowsum: one thread per (bh, t)
// ---------------------------------------------------------------------------
__global__ void __launch_bounds__(256) rowsum_inv()
{
    const int row = blockIdx.x * 256 + threadIdx.x;
    if (row >= BH_ * T_) return;
    const float4* p = (const float4*)&g_psum[(size_t)row * NTILE];
    float4 a = p[0], b = p[1], c = p[2], d = p[3];
    float s = ((a.x + a.y) + (a.z + a.w)) + ((b.x + b.y) + (b.z + b.w))
            + ((c.x + c.y) + (c.z + c.w)) + ((d.x + d.y) + (d.z + d.w));
    g_rsi[row] = 1.0f / s;
}

// ---------------------------------------------------------------------------
// attn_weights[b,tq,ts] = (1/H) * sum_h expS[b,h,tq,ts] * rsi[b,h,tq]
// ---------------------------------------------------------------------------
__global__ void __launch_bounds__(256) head_sum(const float* __restrict__ P,
                                                float* __restrict__ W)
{
    const size_t idx = (size_t)blockIdx.x * blockDim.x + threadIdx.x; // float4 units
    const size_t per_b = (size_t)T_ * T_ / 4;
    const size_t total = (size_t)B_ * per_b;
    if (idx >= total) return;
    const size_t b   = idx / per_b;
    const size_t rem = idx % per_b;
    const int    tq  = (int)(rem / (T_ / 4));
    const float4* base = (const float4*)P + b * H_ * per_b + rem;
    float4 s = make_float4(0.f, 0.f, 0.f, 0.f);
    #pragma unroll
    for (int h = 0; h < H_; h++) {
        float4 x = base[(size_t)h * per_b];
        const float inv = g_rsi[((size_t)b * H_ + h) * T_ + tq];
        s.x += x.x * inv; s.y += x.y * inv; s.z += x.z * inv; s.w += x.w * inv;
    }
    const float sc = 1.0f / (float)H_;
    s.x *= sc; s.y *= sc; s.z *= sc; s.w *= sc;
    ((float4*)W)[idx] = s;
}

// ---------------------------------------------------------------------------
extern "C" void kernel_launch(void* const* d_in, const int* in_sizes, int n_in,
                              void* d_out, int out_size)
{
    const float* x     = (const float*)d_in[0];
    const float* in_w  = (const float*)d_in[1];
    const float* in_b  = (const float*)d_in[2];
    const float* out_w = (const float*)d_in[3];
    const float* out_b = (const float*)d_in[4];

    float* attn_out = (float*)d_out;                        // [T,B,E]
    float* w_out    = (float*)d_out + (size_t)MTOK * E_;    // [B,T,T]

    float *Q, *K, *V, *P, *ATT;
    cudaGetSymbolAddress((void**)&Q,   g_Q);
    cudaGetSymbolAddress((void**)&K,   g_K);
    cudaGetSymbolAddress((void**)&V,   g_V);
    cudaGetSymbolAddress((void**)&P,   g_P);
    cudaGetSymbolAddress((void**)&ATT, g_ATT);

    // 1) QKV projection (tf32 mma) -> g_Q/g_K/g_V
    gemm_mma<128,128,64,32,0,true><<<dim3(N3E/128, MTOK/128), 256>>>(
        x, in_w, in_b, nullptr, MTOK, N3E, E_);
    // 2) expS = exp(Q @ K^T) per (b,h), with per-tile row sums
    gemm_mma<128,128,64,32,2,true><<<dim3(T_/128, T_/128, BH_), 256>>>(
        Q, K, nullptr, P, T_, T_, HD_);
    // 3) inverse row sums
    rowsum_inv<<<(BH_ * T_ + 255) / 256, 256>>>();
    // 4) head-averaged attention weights -> second output
    {
        const size_t total4 = (size_t)B_ * T_ * T_ / 4;
        head_sum<<<(unsigned)((total4 + 255) / 256), 256>>>(P, w_out);
    }
    // 5) O = (expS @ V) * rsi, written in [T,B,E] layout
    gemm_mma<128,64,32,32,3,false><<<dim3(1, T_/128, BH_), 256>>>(
        P, V, nullptr, ATT, T_, HD_, T_);
    // 6) out projection -> first output
    gemm_mma<128,128,64,32,1,true><<<dim3(E_/128, MTOK/128), 256>>>(
        ATT, out_w, out_b, attn_out, MTOK, E_, E_);
}

// round 5
// speedup vs baseline: 4.1627x; 1.3659x over previous
#include <cuda_runtime.h>
#include <cuda_fp16.h>
#include <math.h>
#include <stdint.h>

static constexpr int T_   = 2048;
static constexpr int B_   = 2;
static constexpr int E_   = 1024;
static constexpr int H_   = 16;
static constexpr int HD_  = 64;
static constexpr int MTOK = T_ * B_;   // 4096
static constexpr int BH_  = B_ * H_;   // 32
static constexpr int N3E  = 3 * E_;    // 3072
static constexpr int NTILE = T_ / 128; // 16 score col-tiles per row

// Scratch (static device globals: allocation-free at launch time)
__device__ __half g_Q[(size_t)BH_ * T_ * HD_];
__device__ __half g_K[(size_t)BH_ * T_ * HD_];
__device__ __half g_V[(size_t)BH_ * T_ * HD_];
__device__ __half g_P[(size_t)BH_ * T_ * T_];      // unnormalized exp(scores), fp16
__device__ __half g_ATT[(size_t)MTOK * E_];
__device__ float  g_psum[(size_t)BH_ * T_ * NTILE];
__device__ float  g_rsi[(size_t)BH_ * T_];

__device__ __forceinline__ uint32_t pack_h2(float a, float b) {
    __half2 h = __floats2half2_rn(a, b);
    return *(uint32_t*)&h;
}

__device__ __forceinline__ void mma_f16(float* d, const uint32_t* a, const uint32_t* b) {
    asm volatile(
        "mma.sync.aligned.m16n8k16.row.col.f32.f16.f16.f32 "
        "{%0,%1,%2,%3}, {%4,%5,%6,%7}, {%8,%9}, {%0,%1,%2,%3};"
        : "+f"(d[0]), "+f"(d[1]), "+f"(d[2]), "+f"(d[3])
        : "r"(a[0]), "r"(a[1]), "r"(a[2]), "r"(a[3]), "r"(b[0]), "r"(b[1]));
}

// ---------------------------------------------------------------------------
// FP16 tensor-core GEMM (fp32 accumulate). C = A(MxK) @ op(B).
//  BTRANS=true : B given (N x K) row-major (C = A B^T)
//  BTRANS=false: B given (K x N) row-major (PV; transposed at smem store)
//  AF32/BF32   : gmem dtype of A/B (fp32 converted to half at smem store)
// MODE 0: QKV epilogue (bias + scatter half Q/K/V, q*scale)
// MODE 1: out-proj epilogue (bias, fp32 row-major C)
// MODE 2: batched scores: fused exp, half P, per-tile row sums -> g_psum
// MODE 3: batched PV, rows scaled by g_rsi, half scatter to [T,B,E]
// Block: BM x BN x 32, 256 threads, mma m16n8k16.
// ---------------------------------------------------------------------------
template <int BM, int BN, int WM, int WN, int MODE, bool BTRANS, bool AF32, bool BF32>
__global__ void __launch_bounds__(256) gemm_mma(
    const void* __restrict__ Av, const void* __restrict__ Bv,
    const float* __restrict__ bias, void* __restrict__ Cv,
    int M, int N, int K)
{
    constexpr int KC   = 32;         // k-chunk in elements
    constexpr int SROW = 20;         // b32 per smem row (32 halves + 8 pad)
    constexpr int WARPS_N = BN / WN;
    constexpr int MT = WM / 16;
    constexpr int NT = WN / 8;

    __shared__ uint32_t As[BM][SROW];
    __shared__ uint32_t Bs[BN][SROW];
    __shared__ float Ssum[MODE == 2 ? BM : 1][MODE == 2 ? WARPS_N : 1];

    const float*  Af = (const float*)Av;
    const __half* Ah = (const __half*)Av;
    const float*  Bf = (const float*)Bv;
    const __half* Bh = (const __half*)Bv;

    if (MODE == 2) {
        size_t z = blockIdx.z;
        Ah += z * (size_t)T_ * HD_;
        Bh += z * (size_t)T_ * HD_;
    }
    if (MODE == 3) {
        size_t z = blockIdx.z;
        Ah += z * (size_t)T_ * T_;
        Bh += z * (size_t)T_ * HD_;
    }

    const int tid  = threadIdx.x;
    const int lane = tid & 31;
    const int warp = tid >> 5;
    const int wm   = warp / WARPS_N;
    const int wn   = warp % WARPS_N;
    const int i0   = blockIdx.y * BM;
    const int j0   = blockIdx.x * BN;
    const int lc   = lane & 3;
    const int lg   = lane >> 2;

    float acc[MT][NT][4];
    #pragma unroll
    for (int i = 0; i < MT; i++)
        #pragma unroll
        for (int j = 0; j < NT; j++)
            #pragma unroll
            for (int q = 0; q < 4; q++) acc[i][j][q] = 0.f;

    constexpr int AV4 = AF32 ? BM * KC / 1024 : 1;               // float4 loads
    constexpr int AV8 = AF32 ? 1 : BM * KC / 2048;               // uint4 (8h) loads
    constexpr int BV4 = (BTRANS && BF32) ? BN * KC / 1024 : 1;
    constexpr int BV8 = (BTRANS && !BF32) ? BN * KC / 2048 : 1;
    constexpr int BV2 = (!BTRANS) ? BN * KC / 1024 : 1;          // uint2 (4h) loads

    float4 apf[AV4]; uint4 aph[AV8];
    float4 bpf[BV4]; uint4 bph[BV8]; uint2 bpv[BV2];

    auto loadA = [&](int kt) {
        if (AF32) {
            #pragma unroll
            for (int v = 0; v < AV4; v++) {
                int f = tid + v * 256;
                int row = f >> 3;             // 8 float4 per 32-elem row
                int k4  = (f & 7) << 2;
                apf[v] = *(const float4*)(Af + (size_t)(i0 + row) * K + kt + k4);
            }
        } else {
            #pragma unroll
            for (int v = 0; v < AV8; v++) {
                int f = tid + v * 256;
                int row = f >> 2;             // 4 uint4 per 32-half row
                int k8  = (f & 3) << 3;
                aph[v] = *(const uint4*)(Ah + (size_t)(i0 + row) * K + kt + k8);
            }
        }
    };
    auto storeA = [&]() {
        if (AF32) {
            #pragma unroll
            for (int v = 0; v < AV4; v++) {
                int f = tid + v * 256;
                int row = f >> 3;
                int c2  = (f & 7) << 1;       // b32 col
                uint2 u;
                u.x = pack_h2(apf[v].x, apf[v].y);
                u.y = pack_h2(apf[v].z, apf[v].w);
                *(uint2*)&As[row][c2] = u;
            }
        } else {
            #pragma unroll
            for (int v = 0; v < AV8; v++) {
                int f = tid + v * 256;
                int row = f >> 2;
                int c4  = (f & 3) << 2;
                *(uint4*)&As[row][c4] = aph[v];
            }
        }
    };
    auto loadB = [&](int kt) {
        if (BTRANS) {
            if (BF32) {
                #pragma unroll
                for (int v = 0; v < BV4; v++) {
                    int f = tid + v * 256;
                    int row = f >> 3;
                    int k4  = (f & 7) << 2;
                    bpf[v] = *(const float4*)(Bf + (size_t)(j0 + row) * K + kt + k4);
                }
            } else {
                #pragma unroll
                for (int v = 0; v < BV8; v++) {
                    int f = tid + v * 256;
                    int row = f >> 2;
                    int k8  = (f & 3) << 3;
                    bph[v] = *(const uint4*)(Bh + (size_t)(j0 + row) * K + kt + k8);
                }
            }
        } else {
            #pragma unroll
            for (int v = 0; v < BV2; v++) {
                int f = tid + v * 256;
                int krow = f >> 4;            // 16 uint2 per 64-col k-row
                int n4   = (f & 15) << 2;
                bpv[v] = *(const uint2*)(Bh + (size_t)(kt + krow) * N + j0 + n4);
            }
        }
    };
    auto storeB = [&]() {
        if (BTRANS) {
            if (BF32) {
                #pragma unroll
                for (int v = 0; v < BV4; v++) {
                    int f = tid + v * 256;
                    int row = f >> 3;
                    int c2  = (f & 7) << 1;
                    uint2 u;
                    u.x = pack_h2(bpf[v].x, bpf[v].y);
                    u.y = pack_h2(bpf[v].z, bpf[v].w);
                    *(uint2*)&Bs[row][c2] = u;
                }
            } else {
                #pragma unroll
                for (int v = 0; v < BV8; v++) {
                    int f = tid + v * 256;
                    int row = f >> 2;
                    int c4  = (f & 3) << 2;
                    *(uint4*)&Bs[row][c4] = bph[v];
                }
            }
        } else {
            // transpose 4 halves (one k-row, 4 n-cols) into Bs[n][k]
            __half* bsh = (__half*)Bs;
            #pragma unroll
            for (int v = 0; v < BV2; v++) {
                int f = tid + v * 256;
                int krow = f >> 4;
                int n4   = (f & 15) << 2;
                const __half* hh = (const __half*)&bpv[v];
                #pragma unroll
                for (int e = 0; e < 4; e++)
                    bsh[(size_t)(n4 + e) * (2 * SROW) + krow] = hh[e];
            }
        }
    };

    loadA(0);
    loadB(0);

    for (int kt = 0; kt < K; kt += KC) {
        storeA();
        storeB();
        __syncthreads();
        if (kt + KC < K) { loadA(kt + KC); loadB(kt + KC); }

        #pragma unroll
        for (int s = 0; s < KC / 16; s++) {
            const int kb = s * 8;             // b32 offset of 16-half chunk
            uint32_t af[MT][4];
            uint32_t bf[NT][2];
            #pragma unroll
            for (int i = 0; i < MT; i++) {
                int r = wm * WM + i * 16 + lg;
                af[i][0] = As[r][kb + lc];
                af[i][1] = As[r + 8][kb + lc];
                af[i][2] = As[r][kb + lc + 4];
                af[i][3] = As[r + 8][kb + lc + 4];
            }
            #pragma unroll
            for (int j = 0; j < NT; j++) {
                int n = wn * WN + j * 8 + lg;
                bf[j][0] = Bs[n][kb + lc];
                bf[j][1] = Bs[n][kb + lc + 4];
            }
            #pragma unroll
            for (int i = 0; i < MT; i++)
                #pragma unroll
                for (int j = 0; j < NT; j++)
                    mma_f16(acc[i][j], af[i], bf[j]);
        }
        __syncthreads();
    }

    // --- Epilogue (column pairs: q={2qh, 2qh+1} share row, adjacent cols) ---
    float rowpart[MODE == 2 ? MT : 1][MODE == 2 ? 2 : 1];
    if (MODE == 2) {
        #pragma unroll
        for (int i = 0; i < MT; i++) { rowpart[i][0] = 0.f; rowpart[i][1] = 0.f; }
    }

    #pragma unroll
    for (int i = 0; i < MT; i++) {
        #pragma unroll
        for (int j = 0; j < NT; j++) {
            const int r_lo = i0 + wm * WM + i * 16 + lg;
            const int c    = j0 + wn * WN + j * 8 + lc * 2;  // even
            #pragma unroll
            for (int qh = 0; qh < 2; qh++) {
                const int r = r_lo + qh * 8;
                float v0 = acc[i][j][qh * 2 + 0];
                float v1 = acc[i][j][qh * 2 + 1];
                if (MODE == 0) {
                    v0 += __ldg(&bias[c]);
                    v1 += __ldg(&bias[c + 1]);
                    const int t   = r >> 1;       // B_ == 2
                    const int b   = r & 1;
                    const int seg = c >> 10;
                    const int cc  = c & 1023;
                    const int h   = cc >> 6;
                    const int d   = cc & 63;      // even
                    const size_t off = (((size_t)(b * H_ + h) * T_ + t) * HD_) + d;
                    if (seg == 0) { v0 *= 0.125f; v1 *= 0.125f;
                        *(uint32_t*)&g_Q[off] = pack_h2(v0, v1);
                    } else if (seg == 1) {
                        *(uint32_t*)&g_K[off] = pack_h2(v0, v1);
                    } else {
                        *(uint32_t*)&g_V[off] = pack_h2(v0, v1);
                    }
                } else if (MODE == 1) {
                    float* C = (float*)Cv;
                    float2 w = make_float2(v0 + __ldg(&bias[c]), v1 + __ldg(&bias[c + 1]));
                    *(float2*)&C[(size_t)r * N + c] = w;
                } else if (MODE == 2) {
                    float e0 = __expf(v0), e1 = __expf(v1);
                    __half* C = (__half*)Cv + (size_t)blockIdx.z * T_ * T_;
                    *(uint32_t*)&C[(size_t)r * T_ + c] = pack_h2(e0, e1);
                    rowpart[i][qh] += e0 + e1;
                } else { // MODE 3
                    const int z = blockIdx.z;
                    const int b = z >> 4;
                    const int h = z & 15;
                    const float inv = g_rsi[(size_t)z * T_ + r];
                    __half* C = (__half*)Cv;
                    *(uint32_t*)&C[((size_t)r * B_ + b) * E_ + h * HD_ + c] =
                        pack_h2(v0 * inv, v1 * inv);
                }
            }
        }
    }

    if (MODE == 2) {
        #pragma unroll
        for (int i = 0; i < MT; i++) {
            #pragma unroll
            for (int qh = 0; qh < 2; qh++) {
                float s = rowpart[i][qh];
                s += __shfl_xor_sync(0xffffffffu, s, 1);
                s += __shfl_xor_sync(0xffffffffu, s, 2);
                rowpart[i][qh] = s;
            }
        }
        if (lc == 0) {
            #pragma unroll
            for (int i = 0; i < MT; i++)
                #pragma unroll
                for (int qh = 0; qh < 2; qh++) {
                    int rl = wm * WM + i * 16 + qh * 8 + lg;
                    Ssum[rl][wn] = rowpart[i][qh];
                }
        }
        __syncthreads();
        if (tid < BM) {
            float s = 0.f;
            #pragma unroll
            for (int w = 0; w < WARPS_N; w++) s += Ssum[tid][w];
            g_psum[((size_t)blockIdx.z * T_ + i0 + tid) * NTILE + blockIdx.x] = s;
        }
    }
}

// ---------------------------------------------------------------------------
__global__ void __launch_bounds__(256) rowsum_inv()
{
    const int row = blockIdx.x * 256 + threadIdx.x;
    if (row >= BH_ * T_) return;
    const float4* p = (const float4*)&g_psum[(size_t)row * NTILE];
    float4 a = p[0], b = p[1], c = p[2], d = p[3];
    float s = ((a.x + a.y) + (a.z + a.w)) + ((b.x + b.y) + (b.z + b.w))
            + ((c.x + c.y) + (c.z + c.w)) + ((d.x + d.y) + (d.z + d.w));
    g_rsi[row] = 1.0f / s;
}

// ---------------------------------------------------------------------------
// attn_weights[b,tq,ts] = (1/H) * sum_h expS[b,h,tq,ts] * rsi[b,h,tq]
// 8 halves per thread per head.
// ---------------------------------------------------------------------------
__global__ void __launch_bounds__(256) head_sum(const __half* __restrict__ P,
                                                float* __restrict__ W)
{
    const size_t idx = (size_t)blockIdx.x * 256 + threadIdx.x;   // 8-elem units
    const size_t per_b = (size_t)T_ * T_ / 8;
    if (idx >= (size_t)B_ * per_b) return;
    const size_t b   = idx / per_b;
    const size_t rem = idx % per_b;
    const int    tq  = (int)(rem / (T_ / 8));
    const uint4* base = (const uint4*)P + b * H_ * per_b + rem;
    float acc[8] = {0.f, 0.f, 0.f, 0.f, 0.f, 0.f, 0.f, 0.f};
    #pragma unroll
    for (int h = 0; h < H_; h++) {
        uint4 x = base[(size_t)h * per_b];
        const float inv = g_rsi[((size_t)b * H_ + h) * T_ + tq];
        const __half2* hp = (const __half2*)&x;
        #pragma unroll
        for (int k = 0; k < 4; k++) {
            float2 f = __half22float2(hp[k]);
            acc[2 * k]     += f.x * inv;
            acc[2 * k + 1] += f.y * inv;
        }
    }
    const float sc = 1.0f / (float)H_;
    float4 o0 = make_float4(acc[0] * sc, acc[1] * sc, acc[2] * sc, acc[3] * sc);
    float4 o1 = make_float4(acc[4] * sc, acc[5] * sc, acc[6] * sc, acc[7] * sc);
    ((float4*)W)[idx * 2]     = o0;
    ((float4*)W)[idx * 2 + 1] = o1;
}

// ---------------------------------------------------------------------------
extern "C" void kernel_launch(void* const* d_in, const int* in_sizes, int n_in,
                              void* d_out, int out_size)
{
    const float* x     = (const float*)d_in[0];
    const float* in_w  = (const float*)d_in[1];
    const float* in_b  = (const float*)d_in[2];
    const float* out_w = (const float*)d_in[3];
    const float* out_b = (const float*)d_in[4];

    float* attn_out = (float*)d_out;                        // [T,B,E]
    float* w_out    = (float*)d_out + (size_t)MTOK * E_;    // [B,T,T]

    __half *Q, *K, *V, *P, *ATT;
    cudaGetSymbolAddress((void**)&Q,   g_Q);
    cudaGetSymbolAddress((void**)&K,   g_K);
    cudaGetSymbolAddress((void**)&V,   g_V);
    cudaGetSymbolAddress((void**)&P,   g_P);
    cudaGetSymbolAddress((void**)&ATT, g_ATT);

    // 1) QKV projection (fp32 in, half out)
    gemm_mma<128,128,64,32,0,true,true,true><<<dim3(N3E/128, MTOK/128), 256>>>(
        x, in_w, in_b, nullptr, MTOK, N3E, E_);
    // 2) expS = exp(Q @ K^T) per (b,h), half P + per-tile row sums
    gemm_mma<128,128,64,32,2,true,false,false><<<dim3(T_/128, T_/128, BH_), 256>>>(
        Q, K, nullptr, P, T_, T_, HD_);
    // 3) inverse row sums
    rowsum_inv<<<(BH_ * T_ + 255) / 256, 256>>>();
    // 4) head-averaged attention weights -> second output
    head_sum<<<(unsigned)(((size_t)B_ * T_ * T_ / 8 + 255) / 256), 256>>>(P, w_out);
    // 5) O = (expS @ V) * rsi -> half ATT in [T,B,E]
    gemm_mma<128,64,32,32,3,false,false,false><<<dim3(1, T_/128, BH_), 256>>>(
        P, V, nullptr, ATT, T_, HD_, T_);
    // 6) out projection -> first output (fp32)
    gemm_mma<128,128,64,32,1,true,false,true><<<dim3(E_/128, MTOK/128), 256>>>(
        ATT, out_w, out_b, attn_out, MTOK, E_, E_);
}

// round 6
// speedup vs baseline: 5.4888x; 1.3186x over previous
#include <cuda_runtime.h>
#include <cuda_fp16.h>
#include <math.h>
#include <stdint.h>

static constexpr int T_   = 2048;
static constexpr int B_   = 2;
static constexpr int E_   = 1024;
static constexpr int H_   = 16;
static constexpr int HD_  = 64;
static constexpr int MTOK = T_ * B_;   // 4096
static constexpr int BH_  = B_ * H_;   // 32
static constexpr int N3E  = 3 * E_;    // 3072
static constexpr int NTILE = T_ / 128; // 16 score col-tiles per row

// Scratch (static device globals: allocation-free at launch time)
__device__ __half g_Xh[(size_t)MTOK * E_];          // x in fp16
__device__ __half g_Wh[(size_t)N3E * E_];           // in_proj_w fp16
__device__ __half g_OWh[(size_t)E_ * E_];           // out_w fp16
__device__ __half g_Q[(size_t)BH_ * T_ * HD_];
__device__ __half g_K[(size_t)BH_ * T_ * HD_];
__device__ __half g_Vt[(size_t)BH_ * HD_ * T_];     // V transposed: [b,h,d,t]
__device__ __half g_P[(size_t)BH_ * T_ * T_];       // unnormalized exp(scores)
__device__ __half g_ATT[(size_t)MTOK * E_];
__device__ float  g_psum[(size_t)BH_ * T_ * NTILE];
__device__ float  g_rsi[(size_t)BH_ * T_];

__device__ __forceinline__ uint32_t pack_h2(float a, float b) {
    __half2 h = __floats2half2_rn(a, b);
    return *(uint32_t*)&h;
}

__device__ __forceinline__ void mma_f16(float* d, const uint32_t* a, const uint32_t* b) {
    asm volatile(
        "mma.sync.aligned.m16n8k16.row.col.f32.f16.f16.f32 "
        "{%0,%1,%2,%3}, {%4,%5,%6,%7}, {%8,%9}, {%0,%1,%2,%3};"
        : "+f"(d[0]), "+f"(d[1]), "+f"(d[2]), "+f"(d[3])
        : "r"(a[0]), "r"(a[1]), "r"(a[2]), "r"(a[3]), "r"(b[0]), "r"(b[1]));
}

__device__ __forceinline__ void cp16(void* dst, const void* src) {
    uint32_t d = (uint32_t)__cvta_generic_to_shared(dst);
    asm volatile("cp.async.ca.shared.global [%0], [%1], 16;" :: "r"(d), "l"(src));
}
__device__ __forceinline__ void ldm_x4(uint32_t* r, const void* p) {
    uint32_t a = (uint32_t)__cvta_generic_to_shared(p);
    asm volatile("ldmatrix.sync.aligned.m8n8.x4.shared.b16 {%0,%1,%2,%3}, [%4];"
        : "=r"(r[0]), "=r"(r[1]), "=r"(r[2]), "=r"(r[3]) : "r"(a));
}

// ---------------------------------------------------------------------------
// FP16 tensor-core GEMM, cp.async 2-stage pipeline + ldmatrix fragments.
// C = A(MxK) @ B^T where B is (N x K) row-major. fp32 accumulate.
// MODE 0: QKV epilogue (bias + scatter Q/K scaled + V transposed)
// MODE 1: out-proj epilogue (bias, fp32 row-major C)
// MODE 2: batched scores (z=(b,h)): fused exp, half P, row psums
// MODE 3: batched PV (B = Vt), rows scaled by g_rsi, half -> [T,B,E]
// ---------------------------------------------------------------------------
template <int BM, int BN, int WM, int WN, int MODE>
__global__ void __launch_bounds__(256) gemm_h(
    const __half* __restrict__ A, const __half* __restrict__ Bm,
    const float* __restrict__ bias, void* __restrict__ Cv,
    int M, int N, int K)
{
    constexpr int KC   = 32;
    constexpr int SROW = 20;                 // b32 per smem row (32h + pad)
    constexpr int WARPS_N = BN / WN;
    constexpr int MT = WM / 16;
    constexpr int NT = WN / 8;
    constexpr int NP = NT / 2;               // ldmatrix x4 pairs for B
    constexpr int ACH = BM * 4 / 256;        // 16B chunks per thread (A)
    constexpr int BCH = BN * 4 / 256;

    __shared__ uint32_t As[2][BM][SROW];
    __shared__ uint32_t Bs[2][BN][SROW];
    __shared__ float Ssum[MODE == 2 ? BM : 1][MODE == 2 ? WARPS_N : 1];

    if (MODE == 2) {
        size_t z = blockIdx.z;
        A  += z * (size_t)T_ * HD_;
        Bm += z * (size_t)T_ * HD_;
    }
    if (MODE == 3) {
        size_t z = blockIdx.z;
        A  += z * (size_t)T_ * T_;
        Bm += z * (size_t)HD_ * T_;
    }

    const int tid  = threadIdx.x;
    const int lane = tid & 31;
    const int warp = tid >> 5;
    const int wm   = warp / WARPS_N;
    const int wn   = warp % WARPS_N;
    const int i0   = blockIdx.y * BM;
    const int j0   = blockIdx.x * BN;
    const int lc   = lane & 3;
    const int lg   = lane >> 2;

    // ldmatrix lane address components
    const int lrA = ((lane >> 3) & 1) * 8 + (lane & 7);
    const int lcA = (lane >> 4) * 4;
    const int lrB = ((lane >> 4) & 1) * 8 + (lane & 7);
    const int lcB = ((lane >> 3) & 1) * 4;

    float acc[MT][NT][4];
    #pragma unroll
    for (int i = 0; i < MT; i++)
        #pragma unroll
        for (int j = 0; j < NT; j++)
            #pragma unroll
            for (int q = 0; q < 4; q++) acc[i][j][q] = 0.f;

    auto issue = [&](int st, int kt) {
        #pragma unroll
        for (int v = 0; v < ACH; v++) {
            int f = tid + v * 256;
            int row = f >> 2, ch = f & 3;
            cp16(&As[st][row][ch * 4], A + (size_t)(i0 + row) * K + kt + ch * 8);
        }
        #pragma unroll
        for (int v = 0; v < BCH; v++) {
            int f = tid + v * 256;
            int row = f >> 2, ch = f & 3;
            cp16(&Bs[st][row][ch * 4], Bm + (size_t)(j0 + row) * K + kt + ch * 8);
        }
        asm volatile("cp.async.commit_group;");
    };

    issue(0, 0);
    int st = 0;
    for (int kt = 0; kt < K; kt += KC) {
        if (kt + KC < K) {
            issue(st ^ 1, kt + KC);
            asm volatile("cp.async.wait_group 1;");
        } else {
            asm volatile("cp.async.wait_group 0;");
        }
        __syncthreads();

        #pragma unroll
        for (int s = 0; s < 2; s++) {
            const int kb = s * 8;
            uint32_t af[MT][4], bf[NP][4];
            #pragma unroll
            for (int i = 0; i < MT; i++) {
                int row = wm * WM + i * 16 + lrA;
                ldm_x4(af[i], &As[st][row][kb + lcA]);
            }
            #pragma unroll
            for (int p = 0; p < NP; p++) {
                int row = wn * WN + p * 16 + lrB;
                ldm_x4(bf[p], &Bs[st][row][kb + lcB]);
            }
            #pragma unroll
            for (int i = 0; i < MT; i++)
                #pragma unroll
                for (int j = 0; j < NT; j++)
                    mma_f16(acc[i][j], af[i], &bf[j >> 1][(j & 1) * 2]);
        }
        __syncthreads();
        st ^= 1;
    }

    // --- Epilogue ---
    float rowpart[MODE == 2 ? MT : 1][MODE == 2 ? 2 : 1];
    if (MODE == 2) {
        #pragma unroll
        for (int i = 0; i < MT; i++) { rowpart[i][0] = 0.f; rowpart[i][1] = 0.f; }
    }

    #pragma unroll
    for (int i = 0; i < MT; i++) {
        #pragma unroll
        for (int j = 0; j < NT; j++) {
            const int r_lo = i0 + wm * WM + i * 16 + lg;
            const int c    = j0 + wn * WN + j * 8 + lc * 2;  // even
            #pragma unroll
            for (int qh = 0; qh < 2; qh++) {
                const int r = r_lo + qh * 8;
                float v0 = acc[i][j][qh * 2 + 0];
                float v1 = acc[i][j][qh * 2 + 1];
                if (MODE == 0) {
                    v0 += __ldg(&bias[c]);
                    v1 += __ldg(&bias[c + 1]);
                    const int t   = r >> 1;       // B_ == 2
                    const int b   = r & 1;
                    const int seg = c >> 10;
                    const int cc  = c & 1023;
                    const int h   = cc >> 6;
                    const int d   = cc & 63;      // even
                    if (seg == 0) {
                        const size_t off = (((size_t)(b * H_ + h) * T_ + t) * HD_) + d;
                        *(uint32_t*)&g_Q[off] = pack_h2(v0 * 0.125f, v1 * 0.125f);
                    } else if (seg == 1) {
                        const size_t off = (((size_t)(b * H_ + h) * T_ + t) * HD_) + d;
                        *(uint32_t*)&g_K[off] = pack_h2(v0, v1);
                    } else {
                        // V transposed: [b,h,d,t]
                        const size_t base = ((size_t)(b * H_ + h) * HD_ + d) * T_ + t;
                        g_Vt[base]      = __float2half_rn(v0);
                        g_Vt[base + T_] = __float2half_rn(v1);
                    }
                } else if (MODE == 1) {
                    float* C = (float*)Cv;
                    float2 w = make_float2(v0 + __ldg(&bias[c]), v1 + __ldg(&bias[c + 1]));
                    *(float2*)&C[(size_t)r * N + c] = w;
                } else if (MODE == 2) {
                    float e0 = __expf(v0), e1 = __expf(v1);
                    __half* C = (__half*)Cv + (size_t)blockIdx.z * T_ * T_;
                    *(uint32_t*)&C[(size_t)r * T_ + c] = pack_h2(e0, e1);
                    rowpart[i][qh] += e0 + e1;
                } else { // MODE 3
                    const int z = blockIdx.z;
                    const int b = z >> 4;
                    const int h = z & 15;
                    const float inv = g_rsi[(size_t)z * T_ + r];
                    __half* C = (__half*)Cv;
                    *(uint32_t*)&C[((size_t)r * B_ + b) * E_ + h * HD_ + c] =
                        pack_h2(v0 * inv, v1 * inv);
                }
            }
        }
    }

    if (MODE == 2) {
        #pragma unroll
        for (int i = 0; i < MT; i++) {
            #pragma unroll
            for (int qh = 0; qh < 2; qh++) {
                float s = rowpart[i][qh];
                s += __shfl_xor_sync(0xffffffffu, s, 1);
                s += __shfl_xor_sync(0xffffffffu, s, 2);
                rowpart[i][qh] = s;
            }
        }
        if (lc == 0) {
            #pragma unroll
            for (int i = 0; i < MT; i++)
                #pragma unroll
                for (int qh = 0; qh < 2; qh++) {
                    int rl = wm * WM + i * 16 + qh * 8 + lg;
                    Ssum[rl][wn] = rowpart[i][qh];
                }
        }
        __syncthreads();
        if (tid < BM) {
            float s = 0.f;
            #pragma unroll
            for (int w = 0; w < WARPS_N; w++) s += Ssum[tid][w];
            g_psum[((size_t)blockIdx.z * T_ + i0 + tid) * NTILE + blockIdx.x] = s;
        }
    }
}

// ---------------------------------------------------------------------------
__global__ void __launch_bounds__(256) f32_to_f16(const float* __restrict__ s,
                                                  __half* __restrict__ d, int n)
{
    int i = (blockIdx.x * 256 + threadIdx.x) * 8;
    if (i >= n) return;
    float4 a = *(const float4*)(s + i);
    float4 b = *(const float4*)(s + i + 4);
    uint4 u;
    u.x = pack_h2(a.x, a.y); u.y = pack_h2(a.z, a.w);
    u.z = pack_h2(b.x, b.y); u.w = pack_h2(b.z, b.w);
    *(uint4*)(d + i) = u;
}

// ---------------------------------------------------------------------------
__global__ void __launch_bounds__(256) rowsum_inv()
{
    const int row = blockIdx.x * 256 + threadIdx.x;
    if (row >= BH_ * T_) return;
    const float4* p = (const float4*)&g_psum[(size_t)row * NTILE];
    float4 a = p[0], b = p[1], c = p[2], d = p[3];
    float s = ((a.x + a.y) + (a.z + a.w)) + ((b.x + b.y) + (b.z + b.w))
            + ((c.x + c.y) + (c.z + c.w)) + ((d.x + d.y) + (d.z + d.w));
    g_rsi[row] = 1.0f / s;
}

// ---------------------------------------------------------------------------
// attn_weights[b,tq,ts] = (1/H) * sum_h expS[b,h,tq,ts] * rsi[b,h,tq]
// ---------------------------------------------------------------------------
__global__ void __launch_bounds__(256) head_sum(const __half* __restrict__ P,
                                                float* __restrict__ W)
{
    const size_t idx = (size_t)blockIdx.x * 256 + threadIdx.x;   // 8-elem units
    const size_t per_b = (size_t)T_ * T_ / 8;
    if (idx >= (size_t)B_ * per_b) return;
    const size_t b   = idx / per_b;
    const size_t rem = idx % per_b;
    const int    tq  = (int)(rem / (T_ / 8));
    const uint4* base = (const uint4*)P + b * H_ * per_b + rem;
    float acc[8] = {0.f, 0.f, 0.f, 0.f, 0.f, 0.f, 0.f, 0.f};
    #pragma unroll
    for (int h = 0; h < H_; h++) {
        uint4 x = base[(size_t)h * per_b];
        const float inv = g_rsi[((size_t)b * H_ + h) * T_ + tq];
        const __half2* hp = (const __half2*)&x;
        #pragma unroll
        for (int k = 0; k < 4; k++) {
            float2 f = __half22float2(hp[k]);
            acc[2 * k]     += f.x * inv;
            acc[2 * k + 1] += f.y * inv;
        }
    }
    const float sc = 1.0f / (float)H_;
    float4 o0 = make_float4(acc[0] * sc, acc[1] * sc, acc[2] * sc, acc[3] * sc);
    float4 o1 = make_float4(acc[4] * sc, acc[5] * sc, acc[6] * sc, acc[7] * sc);
    ((float4*)W)[idx * 2]     = o0;
    ((float4*)W)[idx * 2 + 1] = o1;
}

// ---------------------------------------------------------------------------
extern "C" void kernel_launch(void* const* d_in, const int* in_sizes, int n_in,
                              void* d_out, int out_size)
{
    const float* x     = (const float*)d_in[0];
    const float* in_w  = (const float*)d_in[1];
    const float* in_b  = (const float*)d_in[2];
    const float* out_w = (const float*)d_in[3];
    const float* out_b = (const float*)d_in[4];

    float* attn_out = (float*)d_out;                        // [T,B,E]
    float* w_out    = (float*)d_out + (size_t)MTOK * E_;    // [B,T,T]

    __half *Xh, *Wh, *OWh, *Q, *K, *Vt, *P, *ATT;
    cudaGetSymbolAddress((void**)&Xh,  g_Xh);
    cudaGetSymbolAddress((void**)&Wh,  g_Wh);
    cudaGetSymbolAddress((void**)&OWh, g_OWh);
    cudaGetSymbolAddress((void**)&Q,   g_Q);
    cudaGetSymbolAddress((void**)&K,   g_K);
    cudaGetSymbolAddress((void**)&Vt,  g_Vt);
    cudaGetSymbolAddress((void**)&P,   g_P);
    cudaGetSymbolAddress((void**)&ATT, g_ATT);

    // 0) fp32 -> fp16 conversions
    f32_to_f16<<<(MTOK * E_ / 8 + 255) / 256, 256>>>(x, Xh, MTOK * E_);
    f32_to_f16<<<(N3E * E_ / 8 + 255) / 256, 256>>>(in_w, Wh, N3E * E_);
    f32_to_f16<<<(E_ * E_ / 8 + 255) / 256, 256>>>(out_w, OWh, E_ * E_);

    // 1) QKV projection -> Q, K (head layout), Vt (transposed)
    gemm_h<128,128,64,32,0><<<dim3(N3E/128, MTOK/128), 256>>>(
        Xh, Wh, in_b, nullptr, MTOK, N3E, E_);
    // 2) expS = exp(Q @ K^T) per (b,h), half P + per-tile row sums
    gemm_h<128,128,64,32,2><<<dim3(T_/128, T_/128, BH_), 256>>>(
        Q, K, nullptr, P, T_, T_, HD_);
    // 3) inverse row sums
    rowsum_inv<<<(BH_ * T_ + 255) / 256, 256>>>();
    // 4) head-averaged attention weights -> second output
    head_sum<<<(unsigned)(((size_t)B_ * T_ * T_ / 8 + 255) / 256), 256>>>(P, w_out);
    // 5) O = (expS @ Vt^T) * rsi -> half ATT in [T,B,E]
    gemm_h<128,64,32,32,3><<<dim3(1, T_/128, BH_), 256>>>(
        P, Vt, nullptr, ATT, T_, HD_, T_);
    // 6) out projection -> first output (fp32)
    gemm_h<128,128,64,32,1><<<dim3(E_/128, MTOK/128), 256>>>(
        ATT, OWh, out_b, attn_out, MTOK, E_, E_);
}

// round 8
// speedup vs baseline: 5.6613x; 1.0314x over previous
#include <cuda_runtime.h>
#include <cuda_fp16.h>
#include <math.h>
#include <stdint.h>

static constexpr int T_   = 2048;
static constexpr int B_   = 2;
static constexpr int E_   = 1024;
static constexpr int H_   = 16;
static constexpr int HD_  = 64;
static constexpr int MTOK = T_ * B_;   // 4096
static constexpr int BH_  = B_ * H_;   // 32
static constexpr int N3E  = 3 * E_;    // 3072
static constexpr int NTILE = T_ / 128;

// Scratch (static device globals: allocation-free at launch time)
__device__ __half g_Xh[(size_t)MTOK * E_];
__device__ __half g_Wh[(size_t)N3E * E_];
__device__ __half g_OWh[(size_t)E_ * E_];
__device__ __half g_Q[(size_t)BH_ * T_ * HD_];
__device__ __half g_K[(size_t)BH_ * T_ * HD_];
__device__ __half g_Vt[(size_t)BH_ * HD_ * T_];   // [b,h,d,t]
__device__ __half g_P[(size_t)BH_ * T_ * T_];
__device__ __half g_ATT[(size_t)MTOK * E_];
__device__ float  g_psum[(size_t)BH_ * T_ * NTILE];
__device__ float  g_rsi[(size_t)BH_ * T_];

__device__ __forceinline__ uint32_t pack_h2(float a, float b) {
    __half2 h = __floats2half2_rn(a, b);
    return *(uint32_t*)&h;
}
__device__ __forceinline__ void mma_f16(float* d, const uint32_t* a, const uint32_t* b) {
    asm volatile(
        "mma.sync.aligned.m16n8k16.row.col.f32.f16.f16.f32 "
        "{%0,%1,%2,%3}, {%4,%5,%6,%7}, {%8,%9}, {%0,%1,%2,%3};"
        : "+f"(d[0]), "+f"(d[1]), "+f"(d[2]), "+f"(d[3])
        : "r"(a[0]), "r"(a[1]), "r"(a[2]), "r"(a[3]), "r"(b[0]), "r"(b[1]));
}
__device__ __forceinline__ void cp16(uint32_t dst, const void* src) {
    asm volatile("cp.async.cg.shared.global [%0], [%1], 16;" :: "r"(dst), "l"(src));
}
__device__ __forceinline__ void ldm_x4(uint32_t* r, uint32_t a) {
    asm volatile("ldmatrix.sync.aligned.m8n8.x4.shared.b16 {%0,%1,%2,%3}, [%4];"
        : "=r"(r[0]), "=r"(r[1]), "=r"(r[2]), "=r"(r[3]) : "r"(a));
}

// ---------------------------------------------------------------------------
// FP16 HMMA GEMM, 4-stage cp.async ring, one barrier per K-chunk.
// C = A(MxK) @ B^T, B is (N x K) row-major, fp32 accumulate.
// MODE 0: QKV epilogue (bias + Q/K head-scatter + Vt transpose)
// MODE 1: out-proj (bias, fp32 row-major)
// MODE 2: batched scores (z=(b,h)): fused exp, half P, per-tile row psums
// MODE 3: batched PV (B = Vt): rsi-scaled, half -> [T,B,E]
// ---------------------------------------------------------------------------
template <int BM, int BN, int WM, int WN, int MODE>
__global__ void __launch_bounds__(256) gemm_h(
    const __half* __restrict__ A, const __half* __restrict__ Bm,
    const float* __restrict__ bias, void* __restrict__ Cv,
    int M, int N, int K)
{
    constexpr int KC   = 32;
    constexpr int SROW = 20;                 // b32 per smem row (32h + pad)
    constexpr int S    = 4;                  // pipeline stages
    constexpr int WARPS_N = BN / WN;
    constexpr int MT = WM / 16;
    constexpr int NT = WN / 8;
    constexpr int NP = NT / 2;
    constexpr int ACH = BM * 4 / 256;        // 16B chunks per thread (A)
    constexpr int BCH = BN * 4 / 256;
    constexpr int ASZ4 = BM * SROW * 4;      // bytes per A stage
    constexpr int BSZ4 = BN * SROW * 4;

    extern __shared__ char sm[];
    __shared__ float Ssum[MODE == 2 ? BM : 1][MODE == 2 ? WARPS_N : 1];

    const uint32_t sbA = (uint32_t)__cvta_generic_to_shared(sm);
    const uint32_t sbB = sbA + S * ASZ4;

    if (MODE == 2) {
        size_t z = blockIdx.z;
        A  += z * (size_t)T_ * HD_;
        Bm += z * (size_t)T_ * HD_;
    }
    if (MODE == 3) {
        size_t z = blockIdx.z;
        A  += z * (size_t)T_ * T_;
        Bm += z * (size_t)HD_ * T_;
    }

    const int tid  = threadIdx.x;
    const int lane = tid & 31;
    const int warp = tid >> 5;
    const int wm   = warp / WARPS_N;
    const int wn   = warp % WARPS_N;
    const int i0   = blockIdx.y * BM;
    const int j0   = blockIdx.x * BN;
    const int lc   = lane & 3;
    const int lg   = lane >> 2;
    const int C    = K / KC;

    // ldmatrix lane address components (as validated in Round 6)
    const int lrA = ((lane >> 3) & 1) * 8 + (lane & 7);
    const int lcA = (lane >> 4) * 4;
    const int lrB = ((lane >> 4) & 1) * 8 + (lane & 7);
    const int lcB = ((lane >> 3) & 1) * 4;

    float acc[MT][NT][4];
    #pragma unroll
    for (int i = 0; i < MT; i++)
        #pragma unroll
        for (int j = 0; j < NT; j++)
            #pragma unroll
            for (int q = 0; q < 4; q++) acc[i][j][q] = 0.f;

    auto issue = [&](int st, int c) {
        const int k0 = c * KC;
        #pragma unroll
        for (int v = 0; v < ACH; v++) {
            int f = tid + v * 256;
            int row = f >> 2, ch = f & 3;
            cp16(sbA + st * ASZ4 + (row * SROW + ch * 4) * 4,
                 A + (size_t)(i0 + row) * K + k0 + ch * 8);
        }
        #pragma unroll
        for (int v = 0; v < BCH; v++) {
            int f = tid + v * 256;
            int row = f >> 2, ch = f & 3;
            cp16(sbB + st * BSZ4 + (row * SROW + ch * 4) * 4,
                 Bm + (size_t)(j0 + row) * K + k0 + ch * 8);
        }
        asm volatile("cp.async.commit_group;");
    };

    // prologue: S-1 groups (real chunks first, then empty groups keep order)
    #pragma unroll
    for (int s = 0; s < S - 1; s++) {
        if (s < C) issue(s, s);
        else       asm volatile("cp.async.commit_group;");
    }

    for (int c = 0; c < C; c++) {
        const int st = c & (S - 1);
        asm volatile("cp.async.wait_group %0;" :: "n"(S - 2));
        __syncthreads();
        if (c + S - 1 < C) issue((c + S - 1) & (S - 1), c + S - 1);
        else               asm volatile("cp.async.commit_group;");

        #pragma unroll
        for (int s = 0; s < 2; s++) {
            const int kb = s * 8;
            uint32_t af[MT][4], bf[NP][4];
            #pragma unroll
            for (int i = 0; i < MT; i++) {
                int row = wm * WM + i * 16 + lrA;
                ldm_x4(af[i], sbA + st * ASZ4 + (row * SROW + kb + lcA) * 4);
            }
            #pragma unroll
            for (int p = 0; p < NP; p++) {
                int row = wn * WN + p * 16 + lrB;
                ldm_x4(bf[p], sbB + st * BSZ4 + (row * SROW + kb + lcB) * 4);
            }
            #pragma unroll
            for (int i = 0; i < MT; i++)
                #pragma unroll
                for (int j = 0; j < NT; j++)
                    mma_f16(acc[i][j], af[i], &bf[j >> 1][(j & 1) * 2]);
        }
    }

    // --- Epilogue ---
    float rowpart[MODE == 2 ? MT : 1][MODE == 2 ? 2 : 1];
    if (MODE == 2) {
        #pragma unroll
        for (int i = 0; i < MT; i++) { rowpart[i][0] = 0.f; rowpart[i][1] = 0.f; }
    }

    #pragma unroll
    for (int i = 0; i < MT; i++) {
        #pragma unroll
        for (int j = 0; j < NT; j++) {
            const int r_lo = i0 + wm * WM + i * 16 + lg;
            const int c    = j0 + wn * WN + j * 8 + lc * 2;  // even
            #pragma unroll
            for (int qh = 0; qh < 2; qh++) {
                const int r = r_lo + qh * 8;
                float v0 = acc[i][j][qh * 2 + 0];
                float v1 = acc[i][j][qh * 2 + 1];
                if (MODE == 0) {
                    v0 += __ldg(&bias[c]);
                    v1 += __ldg(&bias[c + 1]);
                    const int t   = r >> 1;       // B_ == 2
                    const int b   = r & 1;
                    const int seg = c >> 10;
                    const int cc  = c & 1023;
                    const int h   = cc >> 6;
                    const int d   = cc & 63;      // even
                    if (seg == 0) {
                        const size_t off = (((size_t)(b * H_ + h) * T_ + t) * HD_) + d;
                        *(uint32_t*)&g_Q[off] = pack_h2(v0 * 0.125f, v1 * 0.125f);
                    } else if (seg == 1) {
                        const size_t off = (((size_t)(b * H_ + h) * T_ + t) * HD_) + d;
                        *(uint32_t*)&g_K[off] = pack_h2(v0, v1);
                    } else {
                        const size_t base = ((size_t)(b * H_ + h) * HD_ + d) * T_ + t;
                        g_Vt[base]      = __float2half_rn(v0);
                        g_Vt[base + T_] = __float2half_rn(v1);
                    }
                } else if (MODE == 1) {
                    float* Co = (float*)Cv;
                    float2 w = make_float2(v0 + __ldg(&bias[c]), v1 + __ldg(&bias[c + 1]));
                    *(float2*)&Co[(size_t)r * N + c] = w;
                } else if (MODE == 2) {
                    float e0 = __expf(v0), e1 = __expf(v1);
                    __half* Co = (__half*)Cv + (size_t)blockIdx.z * T_ * T_;
                    *(uint32_t*)&Co[(size_t)r * T_ + c] = pack_h2(e0, e1);
                    rowpart[i][qh] += e0 + e1;
                } else { // MODE 3
                    const int z = blockIdx.z;
                    const int b = z >> 4;
                    const int h = z & 15;
                    const float inv = g_rsi[(size_t)z * T_ + r];
                    __half* Co = (__half*)Cv;
                    *(uint32_t*)&Co[((size_t)r * B_ + b) * E_ + h * HD_ + c] =
                        pack_h2(v0 * inv, v1 * inv);
                }
            }
        }
    }

    if (MODE == 2) {
        #pragma unroll
        for (int i = 0; i < MT; i++) {
            #pragma unroll
            for (int qh = 0; qh < 2; qh++) {
                float s = rowpart[i][qh];
                s += __shfl_xor_sync(0xffffffffu, s, 1);
                s += __shfl_xor_sync(0xffffffffu, s, 2);
                rowpart[i][qh] = s;
            }
        }
        if (lc == 0) {
            #pragma unroll
            for (int i = 0; i < MT; i++)
                #pragma unroll
                for (int qh = 0; qh < 2; qh++) {
                    int rl = wm * WM + i * 16 + qh * 8 + lg;
                    Ssum[rl][wn] = rowpart[i][qh];
                }
        }
        __syncthreads();
        if (tid < BM) {
            float s = 0.f;
            #pragma unroll
            for (int w = 0; w < WARPS_N; w++) s += Ssum[tid][w];
            g_psum[((size_t)blockIdx.z * T_ + i0 + tid) * NTILE + blockIdx.x] = s;
        }
    }
}

// ---------------------------------------------------------------------------
__global__ void __launch_bounds__(256) f32_to_f16(const float* __restrict__ s,
                                                  __half* __restrict__ d, int n)
{
    int i = (blockIdx.x * 256 + threadIdx.x) * 8;
    if (i >= n) return;
    float4 a = *(const float4*)(s + i);
    float4 b = *(const float4*)(s + i + 4);
    uint4 u;
    u.x = pack_h2(a.x, a.y); u.y = pack_h2(a.z, a.w);
    u.z = pack_h2(b.x, b.y); u.w = pack_h2(b.z, b.w);
    *(uint4*)(d + i) = u;
}

__global__ void __launch_bounds__(256) rowsum_inv()
{
    const int row = blockIdx.x * 256 + threadIdx.x;
    if (row >= BH_ * T_) return;
    const float4* p = (const float4*)&g_psum[(size_t)row * NTILE];
    float4 a = p[0], b = p[1], c = p[2], d = p[3];
    float s = ((a.x + a.y) + (a.z + a.w)) + ((b.x + b.y) + (b.z + b.w))
            + ((c.x + c.y) + (c.z + c.w)) + ((d.x + d.y) + (d.z + d.w));
    g_rsi[row] = 1.0f / s;
}

__global__ void __launch_bounds__(256) head_sum(const __half* __restrict__ P,
                                                float* __restrict__ W)
{
    const size_t idx = (size_t)blockIdx.x * 256 + threadIdx.x;   // 8-elem units
    const size_t per_b = (size_t)T_ * T_ / 8;
    if (idx >= (size_t)B_ * per_b) return;
    const size_t b   = idx / per_b;
    const size_t rem = idx % per_b;
    const int    tq  = (int)(rem / (T_ / 8));
    const uint4* base = (const uint4*)P + b * H_ * per_b + rem;
    float acc[8] = {0.f, 0.f, 0.f, 0.f, 0.f, 0.f, 0.f, 0.f};
    #pragma unroll
    for (int h = 0; h < H_; h++) {
        uint4 x = base[(size_t)h * per_b];
        const float inv = g_rsi[((size_t)b * H_ + h) * T_ + tq];
        const __half2* hp = (const __half2*)&x;
        #pragma unroll
        for (int k = 0; k < 4; k++) {
            float2 f = __half22float2(hp[k]);
            acc[2 * k]     += f.x * inv;
            acc[2 * k + 1] += f.y * inv;
        }
    }
    const float sc = 1.0f / (float)H_;
    float4 o0 = make_float4(acc[0] * sc, acc[1] * sc, acc[2] * sc, acc[3] * sc);
    float4 o1 = make_float4(acc[4] * sc, acc[5] * sc, acc[6] * sc, acc[7] * sc);
    ((float4*)W)[idx * 2]     = o0;
    ((float4*)W)[idx * 2 + 1] = o1;
}

// ---------------------------------------------------------------------------
extern "C" void kernel_launch(void* const* d_in, const int* in_sizes, int n_in,
                              void* d_out, int out_size)
{
    const float* x     = (const float*)d_in[0];
    const float* in_w  = (const float*)d_in[1];
    const float* in_b  = (const float*)d_in[2];
    const float* out_w = (const float*)d_in[3];
    const float* out_b = (const float*)d_in[4];

    float* attn_out = (float*)d_out;                        // [T,B,E]
    float* w_out    = (float*)d_out + (size_t)MTOK * E_;    // [B,T,T]

    __half *Xh, *Wh, *OWh, *Q, *K, *Vt, *P, *ATT;
    cudaGetSymbolAddress((void**)&Xh,  g_Xh);
    cudaGetSymbolAddress((void**)&Wh,  g_Wh);
    cudaGetSymbolAddress((void**)&OWh, g_OWh);
    cudaGetSymbolAddress((void**)&Q,   g_Q);
    cudaGetSymbolAddress((void**)&K,   g_K);
    cudaGetSymbolAddress((void**)&Vt,  g_Vt);
    cudaGetSymbolAddress((void**)&P,   g_P);
    cudaGetSymbolAddress((void**)&ATT, g_ATT);

    constexpr int SM_128 = 4 * (128 * 20 + 128 * 20) * 4;   // 81920
    constexpr int SM_64  = 4 * (128 * 20 + 64 * 20) * 4;    // 61440
    cudaFuncSetAttribute((const void*)gemm_h<128,128,64,32,0>,
                         cudaFuncAttributeMaxDynamicSharedMemorySize, SM_128);
    cudaFuncSetAttribute((const void*)gemm_h<128,128,64,32,1>,
                         cudaFuncAttributeMaxDynamicSharedMemorySize, SM_128);
    cudaFuncSetAttribute((const void*)gemm_h<128,128,64,32,2>,
                         cudaFuncAttributeMaxDynamicSharedMemorySize, SM_128);
    cudaFuncSetAttribute((const void*)gemm_h<128,64,32,32,3>,
                         cudaFuncAttributeMaxDynamicSharedMemorySize, SM_64);

    // 0) fp32 -> fp16 conversions
    f32_to_f16<<<(MTOK * E_ / 8 + 255) / 256, 256>>>(x, Xh, MTOK * E_);
    f32_to_f16<<<(N3E * E_ / 8 + 255) / 256, 256>>>(in_w, Wh, N3E * E_);
    f32_to_f16<<<(E_ * E_ / 8 + 255) / 256, 256>>>(out_w, OWh, E_ * E_);

    // 1) QKV projection -> Q, K (head layout), Vt (transposed)
    gemm_h<128,128,64,32,0><<<dim3(N3E/128, MTOK/128), 256, SM_128>>>(
        Xh, Wh, in_b, nullptr, MTOK, N3E, E_);
    // 2) expS = exp(Q @ K^T) per (b,h) + per-tile row sums
    gemm_h<128,128,64,32,2><<<dim3(T_/128, T_/128, BH_), 256, SM_128>>>(
        Q, K, nullptr, P, T_, T_, HD_);
    // 3) inverse row sums
    rowsum_inv<<<(BH_ * T_ + 255) / 256, 256>>>();
    // 4) head-averaged attention weights -> second output
    head_sum<<<(unsigned)(((size_t)B_ * T_ * T_ / 8 + 255) / 256), 256>>>(P, w_out);
    // 5) O = (expS @ Vt^T) * rsi -> half ATT in [T,B,E]
    gemm_h<128,64,32,32,3><<<dim3(1, T_/128, BH_), 256, SM_64>>>(
        P, Vt, nullptr, ATT, T_, HD_, T_);
    // 6) out projection -> first output (fp32)
    gemm_h<128,128,64,32,1><<<dim3(E_/128, MTOK/128), 256, SM_128>>>(
        ATT, OWh, out_b, attn_out, MTOK, E_, E_);
}